// round 4
// baseline (speedup 1.0000x reference)
#include <cuda_runtime.h>
#include <cuda_bf16.h>
#include <math.h>

#define NS 256   // B*K samples
#define NF 256   // FEATURE_DIM
#define GR 100   // grid size

// ---------------- device scratch (static; no allocations) ----------------
__device__ float d_MYT[GR * NS];       // [y][s]  resized obj y-profile
__device__ float d_MXT[GR * NS];       // [x][s]  resized obj x-profile
__device__ float d_HY[GR];             // resized human y-profile
__device__ float d_HX[GR];
__device__ float d_Kc[32 * 25];        // composite 5x5 adjoint kernel per o2 (u = d+e in [-2,2]^2)
__device__ float d_CT[32 * 5];         // border-correction kernels
__device__ float d_CB[32 * 5];
__device__ float d_CL[32 * 5];
__device__ float d_CR[32 * 5];
__device__ float d_K00[32], d_K01[32], d_K10[32], d_K11[32];  // corner add-backs
__device__ float d_C1[16 * GR * GR];   // conv1 of shared human map (+b1)
__device__ float d_S[32 * GR * GR];    // conv2(C1)+b2 (shared across samples)
__device__ float d_V[(size_t)NF * GR * NS];    // [f][y][s] = sum_x adj[f,y,x]*mx[s,x]
__device__ float d_constPart[NF * 4];  // per-(f,strip) partial <P[f],S>

// 1D bilinear-resize (antialias=False) weight of interval [a,b) at output index yp.
// sample_f = (yp+0.5)*(in/out) - 0.5 ; two-tap triangle; samples interior since g>=100.
__device__ __forceinline__ float fuzzy(int yp, float inv, int a, int b, int G) {
    float sf = ((float)yp + 0.5f) * inv - 0.5f;
    float fl = floorf(sf);
    int i0 = (int)fl;
    float t = sf - fl;
    float v0 = (i0 >= a && i0 < b && i0 < G) ? 1.f : 0.f;  // a>=0 always
    int i1 = i0 + 1;
    float v1 = (i1 >= a && i1 < b && i1 < G) ? 1.f : 0.f;
    return (1.f - t) * v0 + t * v1;
}

// ---------------- k_prep: 1D profiles + composite/correction kernels ----------------
__global__ void k_prep(const int* __restrict__ ox, const int* __restrict__ oy,
                       const int* __restrict__ ow, const int* __restrict__ oh,
                       const int* __restrict__ ghp, const int* __restrict__ gwp,
                       const float* __restrict__ w1, const float* __restrict__ w2) {
    int Gh = ghp[0], Gw = gwp[0];
    float invy = (float)Gh / 100.0f;
    float invx = (float)Gw / 100.0f;
    int tid = threadIdx.x;

    for (int i = tid; i < GR; i += blockDim.x) {
        d_HY[i] = fuzzy(i, invy, 0, 100, Gh);
        d_HX[i] = fuzzy(i, invx, 0, 100, Gw);
    }
    for (int i = tid; i < GR * NS; i += blockDim.x) {
        int y = i / NS, s = i % NS;
        d_MYT[i] = fuzzy(y, invy, oy[s], oy[s] + oh[s], Gh);
        d_MXT[i] = fuzzy(y, invx, ox[s], ox[s] + ow[s], Gw);
    }
    // Kc[o2][uy+2][ux+2] = sum_{o1, d+e=u} w1[o1,1,d] * w2[o2,o1,e]
    for (int i = tid; i < 32 * 25; i += blockDim.x) {
        int o2 = i / 25, uy = (i % 25) / 5 - 2, ux = (i % 25) % 5 - 2;
        float acc = 0.f;
        for (int o1 = 0; o1 < 16; o1++)
            for (int dy = -1; dy <= 1; dy++) {
                int ey = uy - dy; if (ey < -1 || ey > 1) continue;
                for (int dx = -1; dx <= 1; dx++) {
                    int ex = ux - dx; if (ex < -1 || ex > 1) continue;
                    acc += w1[((o1 * 2 + 1) * 3 + dy + 1) * 3 + dx + 1]
                         * w2[((o2 * 16 + o1) * 3 + ey + 1) * 3 + ex + 1];
                }
            }
        d_Kc[i] = acc;
    }
    // Edge corrections. The composite erroneously includes terms where the
    // intermediate index (m-d) falls outside the canvas; those happen only at
    // m_y in {0,99} (rows, via dy=+1/ey=-1 or dy=-1/ey=+1) and m_x in {0,99}.
    for (int i = tid; i < 32 * 5; i += blockDim.x) {
        int o2 = i / 5, t = i % 5 - 2;     // t = combined offset along the free axis
        float ct = 0.f, cb = 0.f, cl = 0.f, cr = 0.f;
        for (int o1 = 0; o1 < 16; o1++)
            for (int d = -1; d <= 1; d++) {
                int e = t - d; if (e < -1 || e > 1) continue;
                ct += w1[((o1 * 2 + 1) * 3 + 2) * 3 + d + 1] * w2[((o2 * 16 + o1) * 3 + 0) * 3 + e + 1];
                cb += w1[((o1 * 2 + 1) * 3 + 0) * 3 + d + 1] * w2[((o2 * 16 + o1) * 3 + 2) * 3 + e + 1];
                cl += w1[((o1 * 2 + 1) * 3 + d + 1) * 3 + 2] * w2[((o2 * 16 + o1) * 3 + e + 1) * 3 + 0];
                cr += w1[((o1 * 2 + 1) * 3 + d + 1) * 3 + 0] * w2[((o2 * 16 + o1) * 3 + e + 1) * 3 + 2];
            }
        d_CT[i] = ct; d_CB[i] = cb; d_CL[i] = cl; d_CR[i] = cr;
    }
    // Corner add-backs (subtracted twice by the two edge corrections)
    for (int o2 = tid; o2 < 32; o2 += blockDim.x) {
        float k00 = 0.f, k01 = 0.f, k10 = 0.f, k11 = 0.f;
        for (int o1 = 0; o1 < 16; o1++) {
            const float* a = &w1[(o1 * 2 + 1) * 9];
            const float* b = &w2[(o2 * 16 + o1) * 9];
            k00 += a[8] * b[0];   // d=(+1,+1), e=(-1,-1)
            k01 += a[6] * b[2];   // d=(+1,-1), e=(-1,+1)
            k10 += a[2] * b[6];   // d=(-1,+1), e=(+1,-1)
            k11 += a[0] * b[8];   // d=(-1,-1), e=(+1,+1)
        }
        d_K00[o2] = k00; d_K01[o2] = k01; d_K10[o2] = k10; d_K11[o2] = k11;
    }
}

// ---------------- k_c1: conv1 (channel 0) of shared human map ----------------
__global__ void k_c1(const float* __restrict__ w1, const float* __restrict__ b1) {
    int o1 = blockIdx.x;
    __shared__ float hyp[102], hxp[102], wk[9];
    int tid = threadIdx.x;
    if (tid < 102) { hyp[tid] = 0.f; hxp[tid] = 0.f; }
    __syncthreads();
    if (tid < GR) { hyp[tid + 1] = d_HY[tid]; hxp[tid + 1] = d_HX[tid]; }
    if (tid < 9) wk[tid] = w1[(o1 * 2 + 0) * 9 + tid];
    __syncthreads();
    float bias = b1[o1];
    for (int p = tid; p < GR * GR; p += blockDim.x) {
        int y = p / GR, x = p % GR;
        float acc = bias;
        #pragma unroll
        for (int ky = 0; ky < 3; ky++)
            #pragma unroll
            for (int kx = 0; kx < 3; kx++)
                acc += wk[ky * 3 + kx] * hyp[y + ky] * hxp[x + kx];
        d_C1[o1 * GR * GR + p] = acc;
    }
}

// ---------------- k_s: S = conv2(C1)+b2 (shared) ----------------
__global__ void k_s(const float* __restrict__ w2, const float* __restrict__ b2) {
    int o2 = blockIdx.x, strip = blockIdx.y, r0 = strip * 25;
    __shared__ float c1p[27][102];
    __shared__ float sac[25][100];
    int tid = threadIdx.x;
    float bias = b2[o2];
    for (int i = tid; i < 2500; i += 256) ((float*)sac)[i] = bias;
    for (int o1 = 0; o1 < 16; o1++) {
        __syncthreads();
        for (int i = tid; i < 27 * 102; i += 256) {
            int r = i / 102, c = i % 102;
            int gy = r0 - 1 + r, gx = c - 1;
            float v = 0.f;
            if (gy >= 0 && gy < GR && gx >= 0 && gx < GR) v = d_C1[o1 * GR * GR + gy * GR + gx];
            c1p[r][c] = v;
        }
        __syncthreads();
        float wk[9];
        #pragma unroll
        for (int q = 0; q < 9; q++) wk[q] = w2[(o2 * 16 + o1) * 9 + q];
        for (int p = tid; p < 2500; p += 256) {
            int ly = p / 100, x = p % 100;
            float acc = 0.f;
            #pragma unroll
            for (int ey = 0; ey < 3; ey++)
                #pragma unroll
                for (int ex = 0; ex < 3; ex++)
                    acc += wk[ey * 3 + ex] * c1p[ly + ey][x + ex];
            sac[ly][x] += acc;
        }
    }
    __syncthreads();
    for (int i = tid; i < 2500; i += 256) {
        int ly = i / 100, x = i % 100;
        d_S[(o2 * GR + r0 + ly) * GR + x] = sac[ly][x];
    }
}

// ---------------- k_main: adjoint via composite 5x5 + const dot + V GEMM ----------------
__global__ void __launch_bounds__(256) k_main(const float* __restrict__ P) {
    int f = blockIdx.x, strip = blockIdx.y, r0 = strip * 25;
    __shared__ __align__(16) float Pp[29][104];   // P plane rows [r0-2, r0+27), cols padded +2 each side
    __shared__ float adjS[25][100];
    __shared__ float sKc[32 * 25];
    __shared__ float sCT[32 * 5], sCB[32 * 5], sCL[32 * 5], sCR[32 * 5];
    __shared__ float sK00[32], sK01[32], sK10[32], sK11[32];
    __shared__ float red[8];
    int tid = threadIdx.x;

    for (int i = tid; i < 2500; i += 256) ((float*)adjS)[i] = 0.f;
    for (int i = tid; i < 800; i += 256) sKc[i] = d_Kc[i];
    if (tid < 160) { sCT[tid] = d_CT[tid]; sCB[tid] = d_CB[tid]; sCL[tid] = d_CL[tid]; sCR[tid] = d_CR[tid]; }
    if (tid < 32) { sK00[tid] = d_K00[tid]; sK01[tid] = d_K01[tid]; sK10[tid] = d_K10[tid]; sK11[tid] = d_K11[tid]; }

    float cacc = 0.f;
    for (int o2 = 0; o2 < 32; o2++) {
        __syncthreads();
        const float* Pplane = P + ((size_t)f * 32 + o2) * 10000;
        for (int i = tid; i < 29 * 104; i += 256) {
            int r = i / 104, c = i % 104;
            int gy = r0 - 2 + r, gx = c - 2;
            float v = 0.f;
            if (gy >= 0 && gy < GR && gx >= 0 && gx < GR) v = Pplane[gy * GR + gx];
            Pp[r][c] = v;
        }
        __syncthreads();

        float kc[25];
        #pragma unroll
        for (int q = 0; q < 25; q++) kc[q] = sKc[o2 * 25 + q];

        // adj[m] += sum_{u in [-2,2]^2} Kc[u] * P[m-u]   (zero-padded plane)
        // register-blocked over 4 consecutive x outputs
        for (int g = tid; g < 625; g += 256) {
            int ly = g / 25, xg = (g % 25) * 4;
            float a0 = 0.f, a1 = 0.f, a2 = 0.f, a3 = 0.f;
            #pragma unroll
            for (int uy = 0; uy < 5; uy++) {
                const float* row = &Pp[ly + 4 - uy][xg];
                float4 rA = *(const float4*)(row);
                float4 rB = *(const float4*)(row + 4);
                float rr[8] = {rA.x, rA.y, rA.z, rA.w, rB.x, rB.y, rB.z, rB.w};
                #pragma unroll
                for (int ux = 0; ux < 5; ux++) {
                    float w = kc[uy * 5 + ux];
                    a0 += w * rr[4 - ux];
                    a1 += w * rr[5 - ux];
                    a2 += w * rr[6 - ux];
                    a3 += w * rr[7 - ux];
                }
            }
            adjS[ly][xg]     += a0;
            adjS[ly][xg + 1] += a1;
            adjS[ly][xg + 2] += a2;
            adjS[ly][xg + 3] += a3;
        }

        // const partial dot <P[f,o2, rows r0..r0+24], S[o2, same rows]>
        for (int i = tid; i < 2500; i += 256) {
            int ly = i / 100, x = i % 100;
            cacc += Pp[ly + 2][x + 2] * d_S[(o2 * GR + r0 + ly) * GR + x];
        }
        __syncthreads();

        // border corrections (rows 0/99 and cols 0/99 only)
        if (strip == 0 && tid < 100) {
            float c = 0.f;
            #pragma unroll
            for (int k = 0; k < 5; k++) c += sCT[o2 * 5 + k] * Pp[2][tid + 4 - k];
            adjS[0][tid] -= c;
        }
        if (strip == 3 && tid < 100) {
            float c = 0.f;
            #pragma unroll
            for (int k = 0; k < 5; k++) c += sCB[o2 * 5 + k] * Pp[26][tid + 4 - k];
            adjS[24][tid] -= c;
        }
        __syncthreads();
        if (tid < 25) {
            float c = 0.f;
            #pragma unroll
            for (int k = 0; k < 5; k++) c += sCL[o2 * 5 + k] * Pp[tid + 4 - k][2];
            adjS[tid][0] -= c;
        } else if (tid >= 32 && tid < 57) {
            int ly = tid - 32;
            float c = 0.f;
            #pragma unroll
            for (int k = 0; k < 5; k++) c += sCR[o2 * 5 + k] * Pp[ly + 4 - k][101];
            adjS[ly][99] -= c;
        }
        __syncthreads();
        if (strip == 0) {
            if (tid == 0) adjS[0][0]  += sK00[o2] * Pp[2][2];
            if (tid == 1) adjS[0][99] += sK01[o2] * Pp[2][101];
        }
        if (strip == 3) {
            if (tid == 0) adjS[24][0]  += sK10[o2] * Pp[26][2];
            if (tid == 1) adjS[24][99] += sK11[o2] * Pp[26][101];
        }
        // top-of-loop sync protects Pp reload & adjS RMW pattern
    }

    // reduce cacc -> d_constPart[f*4+strip]
    unsigned mask = 0xffffffffu;
    #pragma unroll
    for (int off = 16; off > 0; off >>= 1) cacc += __shfl_xor_sync(mask, cacc, off);
    if ((tid & 31) == 0) red[tid >> 5] = cacc;
    __syncthreads();
    if (tid == 0) {
        float t = 0.f;
        #pragma unroll
        for (int i = 0; i < 8; i++) t += red[i];
        d_constPart[f * 4 + strip] = t;
    }
    __syncthreads();   // also guards adjS corner writes before GEMM reads

    // V[f, r0+ly, s] = sum_x adjS[ly][x] * mx[s][x]
    int s = tid;
    for (int ly = 0; ly < 25; ly++) {
        float acc = 0.f;
        #pragma unroll 4
        for (int x = 0; x < 100; x++)
            acc += adjS[ly][x] * d_MXT[x * NS + s];
        d_V[((size_t)f * GR + r0 + ly) * NS + s] = acc;
    }
}

// ---------------- k_final: out[s,f] = pb[f] + <P,S> + sum_y my * V ----------------
__global__ void k_final(const float* __restrict__ pb, float* __restrict__ out) {
    int f = blockIdx.x, s = threadIdx.x;
    float acc = pb[f] + d_constPart[f * 4] + d_constPart[f * 4 + 1]
                      + d_constPart[f * 4 + 2] + d_constPart[f * 4 + 3];
    #pragma unroll 4
    for (int y = 0; y < GR; y++)
        acc += d_MYT[y * NS + s] * d_V[((size_t)f * GR + y) * NS + s];
    out[s * NF + f] = acc;
}

extern "C" void kernel_launch(void* const* d_in, const int* in_sizes, int n_in,
                              void* d_out, int out_size) {
    const int*   ox = (const int*)d_in[0];
    const int*   oy = (const int*)d_in[1];
    const int*   ow = (const int*)d_in[2];
    const int*   oh = (const int*)d_in[3];
    const int*   gh = (const int*)d_in[4];
    const int*   gw = (const int*)d_in[5];
    const float* w1 = (const float*)d_in[6];
    const float* b1 = (const float*)d_in[7];
    const float* w2 = (const float*)d_in[8];
    const float* b2 = (const float*)d_in[9];
    const float* pw = (const float*)d_in[10];
    const float* pb = (const float*)d_in[11];
    float* out = (float*)d_out;

    k_prep<<<1, 256>>>(ox, oy, ow, oh, gh, gw, w1, w2);
    k_c1<<<16, 256>>>(w1, b1);
    k_s<<<dim3(32, 4), 256>>>(w2, b2);
    k_main<<<dim3(NF, 4), 256>>>(pw);
    k_final<<<NF, 256>>>(pb, out);
}

// round 5
// speedup vs baseline: 1.0156x; 1.0156x over previous
#include <cuda_runtime.h>
#include <cuda_bf16.h>
#include <math.h>

#define NS 256   // B*K samples
#define NF 256   // FEATURE_DIM
#define GR 100   // grid size

// ---------------- device scratch (static; no allocations) ----------------
__device__ float d_MYT[GR * NS];       // [y][s]  resized obj y-profile
__device__ float d_MXT[GR * NS];       // [x][s]  resized obj x-profile
__device__ float d_HY[GR];             // resized human y-profile
__device__ float d_HX[GR];
__device__ float d_Kc[32 * 25];        // composite 5x5 adjoint kernel per o2
__device__ float d_CT[32 * 5];         // border-correction kernels
__device__ float d_CB[32 * 5];
__device__ float d_CL[32 * 5];
__device__ float d_CR[32 * 5];
__device__ float d_K00[32], d_K01[32], d_K10[32], d_K11[32];  // corner add-backs
__device__ float d_C1[16 * GR * GR];   // conv1 of shared human map (+b1)
__device__ float d_S[32 * GR * GR];    // conv2(C1)+b2 (shared across samples)
__device__ float d_V[(size_t)NF * GR * NS];    // [f][y][s]
__device__ float d_constPart[NF * 4];  // per-(f,strip) partial <P[f],S>

// 1D bilinear-resize (antialias=False) weight of interval [a,b) at output index yp.
__device__ __forceinline__ float fuzzy(int yp, float inv, int a, int b, int G) {
    float sf = ((float)yp + 0.5f) * inv - 0.5f;
    float fl = floorf(sf);
    int i0 = (int)fl;
    float t = sf - fl;
    float v0 = (i0 >= a && i0 < b && i0 < G) ? 1.f : 0.f;
    int i1 = i0 + 1;
    float v1 = (i1 >= a && i1 < b && i1 < G) ? 1.f : 0.f;
    return (1.f - t) * v0 + t * v1;
}

// ---------------- k_prep: 1D profiles + composite/correction kernels ----------------
__global__ void k_prep(const int* __restrict__ ox, const int* __restrict__ oy,
                       const int* __restrict__ ow, const int* __restrict__ oh,
                       const int* __restrict__ ghp, const int* __restrict__ gwp,
                       const float* __restrict__ w1, const float* __restrict__ w2) {
    int Gh = ghp[0], Gw = gwp[0];
    float invy = (float)Gh / 100.0f;
    float invx = (float)Gw / 100.0f;
    int tid = threadIdx.x;

    for (int i = tid; i < GR; i += blockDim.x) {
        d_HY[i] = fuzzy(i, invy, 0, 100, Gh);
        d_HX[i] = fuzzy(i, invx, 0, 100, Gw);
    }
    for (int i = tid; i < GR * NS; i += blockDim.x) {
        int y = i / NS, s = i % NS;
        d_MYT[i] = fuzzy(y, invy, oy[s], oy[s] + oh[s], Gh);
        d_MXT[i] = fuzzy(y, invx, ox[s], ox[s] + ow[s], Gw);
    }
    for (int i = tid; i < 32 * 25; i += blockDim.x) {
        int o2 = i / 25, uy = (i % 25) / 5 - 2, ux = (i % 25) % 5 - 2;
        float acc = 0.f;
        for (int o1 = 0; o1 < 16; o1++)
            for (int dy = -1; dy <= 1; dy++) {
                int ey = uy - dy; if (ey < -1 || ey > 1) continue;
                for (int dx = -1; dx <= 1; dx++) {
                    int ex = ux - dx; if (ex < -1 || ex > 1) continue;
                    acc += w1[((o1 * 2 + 1) * 3 + dy + 1) * 3 + dx + 1]
                         * w2[((o2 * 16 + o1) * 3 + ey + 1) * 3 + ex + 1];
                }
            }
        d_Kc[i] = acc;
    }
    for (int i = tid; i < 32 * 5; i += blockDim.x) {
        int o2 = i / 5, t = i % 5 - 2;
        float ct = 0.f, cb = 0.f, cl = 0.f, cr = 0.f;
        for (int o1 = 0; o1 < 16; o1++)
            for (int d = -1; d <= 1; d++) {
                int e = t - d; if (e < -1 || e > 1) continue;
                ct += w1[((o1 * 2 + 1) * 3 + 2) * 3 + d + 1] * w2[((o2 * 16 + o1) * 3 + 0) * 3 + e + 1];
                cb += w1[((o1 * 2 + 1) * 3 + 0) * 3 + d + 1] * w2[((o2 * 16 + o1) * 3 + 2) * 3 + e + 1];
                cl += w1[((o1 * 2 + 1) * 3 + d + 1) * 3 + 2] * w2[((o2 * 16 + o1) * 3 + e + 1) * 3 + 0];
                cr += w1[((o1 * 2 + 1) * 3 + d + 1) * 3 + 0] * w2[((o2 * 16 + o1) * 3 + e + 1) * 3 + 2];
            }
        d_CT[i] = ct; d_CB[i] = cb; d_CL[i] = cl; d_CR[i] = cr;
    }
    for (int o2 = tid; o2 < 32; o2 += blockDim.x) {
        float k00 = 0.f, k01 = 0.f, k10 = 0.f, k11 = 0.f;
        for (int o1 = 0; o1 < 16; o1++) {
            const float* a = &w1[(o1 * 2 + 1) * 9];
            const float* b = &w2[(o2 * 16 + o1) * 9];
            k00 += a[8] * b[0];
            k01 += a[6] * b[2];
            k10 += a[2] * b[6];
            k11 += a[0] * b[8];
        }
        d_K00[o2] = k00; d_K01[o2] = k01; d_K10[o2] = k10; d_K11[o2] = k11;
    }
}

// ---------------- k_c1: conv1 (channel 0) of shared human map ----------------
__global__ void k_c1(const float* __restrict__ w1, const float* __restrict__ b1) {
    int o1 = blockIdx.x;
    __shared__ float hyp[102], hxp[102], wk[9];
    int tid = threadIdx.x;
    if (tid < 102) { hyp[tid] = 0.f; hxp[tid] = 0.f; }
    __syncthreads();
    if (tid < GR) { hyp[tid + 1] = d_HY[tid]; hxp[tid + 1] = d_HX[tid]; }
    if (tid < 9) wk[tid] = w1[(o1 * 2 + 0) * 9 + tid];
    __syncthreads();
    float bias = b1[o1];
    for (int p = tid; p < GR * GR; p += blockDim.x) {
        int y = p / GR, x = p % GR;
        float acc = bias;
        #pragma unroll
        for (int ky = 0; ky < 3; ky++)
            #pragma unroll
            for (int kx = 0; kx < 3; kx++)
                acc += wk[ky * 3 + kx] * hyp[y + ky] * hxp[x + kx];
        d_C1[o1 * GR * GR + p] = acc;
    }
}

// ---------------- k_s: S = conv2(C1)+b2 (shared) ----------------
__global__ void k_s(const float* __restrict__ w2, const float* __restrict__ b2) {
    int o2 = blockIdx.x, strip = blockIdx.y, r0 = strip * 25;
    __shared__ float c1p[27][102];
    __shared__ float sac[25][100];
    int tid = threadIdx.x;
    float bias = b2[o2];
    for (int i = tid; i < 2500; i += 256) ((float*)sac)[i] = bias;
    for (int o1 = 0; o1 < 16; o1++) {
        __syncthreads();
        for (int i = tid; i < 27 * 102; i += 256) {
            int r = i / 102, c = i % 102;
            int gy = r0 - 1 + r, gx = c - 1;
            float v = 0.f;
            if (gy >= 0 && gy < GR && gx >= 0 && gx < GR) v = d_C1[o1 * GR * GR + gy * GR + gx];
            c1p[r][c] = v;
        }
        __syncthreads();
        float wk[9];
        #pragma unroll
        for (int q = 0; q < 9; q++) wk[q] = w2[(o2 * 16 + o1) * 9 + q];
        for (int p = tid; p < 2500; p += 256) {
            int ly = p / 100, x = p % 100;
            float acc = 0.f;
            #pragma unroll
            for (int ey = 0; ey < 3; ey++)
                #pragma unroll
                for (int ex = 0; ex < 3; ex++)
                    acc += wk[ey * 3 + ex] * c1p[ly + ey][x + ex];
            sac[ly][x] += acc;
        }
    }
    __syncthreads();
    for (int i = tid; i < 2500; i += 256) {
        int ly = i / 100, x = i % 100;
        d_S[(o2 * GR + r0 + ly) * GR + x] = sac[ly][x];
    }
}

// ---------------- k_main v2: register-tiled composite 5x5 + fused const dot + V GEMM ----------------
__global__ void __launch_bounds__(256) k_main(const float* __restrict__ P) {
    const int f = blockIdx.x, strip = blockIdx.y, r0 = strip * 25;
    __shared__ __align__(16) float Pp[29 * 104];     // padded P plane for current o2
    __shared__ __align__(16) float adjS[25][100];
    __shared__ float sKc[32 * 25];
    __shared__ float sCT[160], sCB[160], sCL[160], sCR[160];
    __shared__ float sK00[32], sK01[32], sK10[32], sK11[32];
    __shared__ float red[8];
    const int tid = threadIdx.x;

    for (int i = tid; i < 800; i += 256) sKc[i] = d_Kc[i];
    if (tid < 160) { sCT[tid] = d_CT[tid]; sCB[tid] = d_CB[tid]; sCL[tid] = d_CL[tid]; sCR[tid] = d_CR[tid]; }
    if (tid < 32) { sK00[tid] = d_K00[tid]; sK01[tid] = d_K01[tid]; sK10[tid] = d_K10[tid]; sK11[tid] = d_K11[tid]; }

    // ---- hoisted staging offsets + validity/interior masks (fixed per thread) ----
    int goff[12];
    unsigned vmask = 0u, imask = 0u;
    #pragma unroll
    for (int j = 0; j < 12; j++) {
        int i = tid + j * 256;
        int r = i / 104, c = i % 104;
        int gy = r0 - 2 + r, gx = c - 2;
        bool inb = (i < 3016);
        goff[j] = gy * 100 + gx;
        if (inb && gy >= 0 && gy < 100 && gx >= 0 && gx < 100) vmask |= (1u << j);
        if (inb && r >= 2 && r < 27 && c >= 2 && c < 102)      imask |= (1u << j);  // interior => valid
    }

    // ---- per-thread output tile: 5 rows x 2 cols ----
    const int ly0 = (tid / 50) * 5;        // 0,5,10,15,20
    const int x0  = (tid % 50) * 2;        // 0..98 even
    const bool active = (tid < 250);

    float acc[5][2];
    #pragma unroll
    for (int r = 0; r < 5; r++) { acc[r][0] = 0.f; acc[r][1] = 0.f; }
    float cacc = 0.f;

    const float* Pf = P + (size_t)f * 320000;

    for (int o2 = 0; o2 < 32; o2++) {
        __syncthreads();                          // previous Pp fully consumed
        const float* Pplane = Pf + o2 * 10000;
        const float* Splane = d_S + o2 * 10000;
        // stage + fused <P,S> partial dot
        #pragma unroll
        for (int j = 0; j < 12; j++) {
            int i = tid + j * 256;
            float v = 0.f;
            if ((vmask >> j) & 1u) v = __ldg(&Pplane[goff[j]]);
            if (i < 3016) Pp[i] = v;
            if ((imask >> j) & 1u) cacc = fmaf(v, __ldg(&Splane[goff[j]]), cacc);
        }
        __syncthreads();

        if (active) {
            float kc[25];
            #pragma unroll
            for (int q = 0; q < 25; q++) kc[q] = sKc[o2 * 25 + q];

            #pragma unroll
            for (int prow = 0; prow < 9; prow++) {
                const float* pr = &Pp[(ly0 + prow) * 104 + x0];
                float2 a0 = *(const float2*)pr;
                float2 a1 = *(const float2*)(pr + 2);
                float2 a2 = *(const float2*)(pr + 4);
                float rv[6] = {a0.x, a0.y, a1.x, a1.y, a2.x, a2.y};
                #pragma unroll
                for (int uy = 0; uy < 5; uy++) {
                    int r = prow - 4 + uy;
                    if (r >= 0 && r < 5) {
                        #pragma unroll
                        for (int ux = 0; ux < 5; ux++) {
                            float w = kc[uy * 5 + ux];
                            acc[r][0] = fmaf(w, rv[4 - ux], acc[r][0]);
                            acc[r][1] = fmaf(w, rv[5 - ux], acc[r][1]);
                        }
                    }
                }
            }

            // ---- border corrections on register accumulators ----
            if (strip == 0 && ly0 == 0) {
                const float* pr = &Pp[2 * 104 + x0];
                float rv[6];
                #pragma unroll
                for (int q = 0; q < 6; q++) rv[q] = pr[q];
                float c0 = 0.f, c1 = 0.f;
                #pragma unroll
                for (int k = 0; k < 5; k++) {
                    float w = sCT[o2 * 5 + k];
                    c0 = fmaf(w, rv[4 - k], c0);
                    c1 = fmaf(w, rv[5 - k], c1);
                }
                acc[0][0] -= c0; acc[0][1] -= c1;
            }
            if (strip == 3 && ly0 == 20) {
                const float* pr = &Pp[26 * 104 + x0];
                float rv[6];
                #pragma unroll
                for (int q = 0; q < 6; q++) rv[q] = pr[q];
                float c0 = 0.f, c1 = 0.f;
                #pragma unroll
                for (int k = 0; k < 5; k++) {
                    float w = sCB[o2 * 5 + k];
                    c0 = fmaf(w, rv[4 - k], c0);
                    c1 = fmaf(w, rv[5 - k], c1);
                }
                acc[4][0] -= c0; acc[4][1] -= c1;
            }
            if (x0 == 0) {
                #pragma unroll
                for (int r = 0; r < 5; r++) {
                    float c = 0.f;
                    #pragma unroll
                    for (int k = 0; k < 5; k++)
                        c = fmaf(sCL[o2 * 5 + k], Pp[(ly0 + r + 4 - k) * 104 + 2], c);
                    acc[r][0] -= c;
                }
            }
            if (x0 == 98) {
                #pragma unroll
                for (int r = 0; r < 5; r++) {
                    float c = 0.f;
                    #pragma unroll
                    for (int k = 0; k < 5; k++)
                        c = fmaf(sCR[o2 * 5 + k], Pp[(ly0 + r + 4 - k) * 104 + 101], c);
                    acc[r][1] -= c;
                }
            }
            if (strip == 0 && ly0 == 0 && x0 == 0)   acc[0][0] = fmaf(sK00[o2], Pp[2 * 104 + 2],   acc[0][0]);
            if (strip == 0 && ly0 == 0 && x0 == 98)  acc[0][1] = fmaf(sK01[o2], Pp[2 * 104 + 101], acc[0][1]);
            if (strip == 3 && ly0 == 20 && x0 == 0)  acc[4][0] = fmaf(sK10[o2], Pp[26 * 104 + 2],  acc[4][0]);
            if (strip == 3 && ly0 == 20 && x0 == 98) acc[4][1] = fmaf(sK11[o2], Pp[26 * 104 + 101], acc[4][1]);
        }
    }

    // ---- single write of adj tile to shared ----
    if (active) {
        #pragma unroll
        for (int r = 0; r < 5; r++) {
            adjS[ly0 + r][x0]     = acc[r][0];
            adjS[ly0 + r][x0 + 1] = acc[r][1];
        }
    }

    // ---- reduce cacc -> d_constPart[f*4+strip] ----
    #pragma unroll
    for (int off = 16; off > 0; off >>= 1) cacc += __shfl_xor_sync(0xffffffffu, cacc, off);
    if ((tid & 31) == 0) red[tid >> 5] = cacc;
    __syncthreads();
    if (tid == 0) {
        float t = 0.f;
        #pragma unroll
        for (int i = 0; i < 8; i++) t += red[i];
        d_constPart[f * 4 + strip] = t;
    }
    __syncthreads();   // adjS visible to all before V GEMM

    // ---- V[f, r0+ly, s] = sum_x adjS[ly][x] * mx[s][x] ----
    float accV[25];
    #pragma unroll
    for (int ly = 0; ly < 25; ly++) accV[ly] = 0.f;
    const float* mxp = d_MXT + tid;
    for (int xc = 0; xc < 25; xc++) {
        float m0 = __ldg(mxp + (4 * xc + 0) * NS);
        float m1 = __ldg(mxp + (4 * xc + 1) * NS);
        float m2 = __ldg(mxp + (4 * xc + 2) * NS);
        float m3 = __ldg(mxp + (4 * xc + 3) * NS);
        #pragma unroll
        for (int ly = 0; ly < 25; ly++) {
            float4 a = *(const float4*)&adjS[ly][xc * 4];
            accV[ly] = fmaf(a.x, m0, fmaf(a.y, m1, fmaf(a.z, m2, fmaf(a.w, m3, accV[ly]))));
        }
    }
    float* vout = d_V + ((size_t)f * GR + r0) * NS + tid;
    #pragma unroll
    for (int ly = 0; ly < 25; ly++) vout[ly * NS] = accV[ly];
}

// ---------------- k_final: out[s,f] = pb[f] + <P,S> + sum_y my * V ----------------
__global__ void k_final(const float* __restrict__ pb, float* __restrict__ out) {
    int f = blockIdx.x, s = threadIdx.x;
    float acc = pb[f] + d_constPart[f * 4] + d_constPart[f * 4 + 1]
                      + d_constPart[f * 4 + 2] + d_constPart[f * 4 + 3];
    #pragma unroll 4
    for (int y = 0; y < GR; y++)
        acc = fmaf(d_MYT[y * NS + s], d_V[((size_t)f * GR + y) * NS + s], acc);
    out[s * NF + f] = acc;
}

extern "C" void kernel_launch(void* const* d_in, const int* in_sizes, int n_in,
                              void* d_out, int out_size) {
    const int*   ox = (const int*)d_in[0];
    const int*   oy = (const int*)d_in[1];
    const int*   ow = (const int*)d_in[2];
    const int*   oh = (const int*)d_in[3];
    const int*   gh = (const int*)d_in[4];
    const int*   gw = (const int*)d_in[5];
    const float* w1 = (const float*)d_in[6];
    const float* b1 = (const float*)d_in[7];
    const float* w2 = (const float*)d_in[8];
    const float* b2 = (const float*)d_in[9];
    const float* pw = (const float*)d_in[10];
    const float* pb = (const float*)d_in[11];
    float* out = (float*)d_out;

    k_prep<<<1, 256>>>(ox, oy, ow, oh, gh, gw, w1, w2);
    k_c1<<<16, 256>>>(w1, b1);
    k_s<<<dim3(32, 4), 256>>>(w2, b2);
    k_main<<<dim3(NF, 4), 256>>>(pw);
    k_final<<<NF, 256>>>(pb, out);
}